// round 6
// baseline (speedup 1.0000x reference)
#include <cuda_runtime.h>

#define Nn      1000
#define INF_    32
#define Hh      128
#define Mm      128
#define DEGc    16
#define Pp      2
#define OUTn    10
#define NSTART  64
#define MAXM    10000
#define QCAP    10016
#define MSGCAP  640
#define Bw      8
#define THRv    (1.0f - 1e-7f)

typedef unsigned long long ull;
typedef unsigned short u16;

__device__ float g_feats[Nn*Hh];
__device__ float g_msgs[MSGCAP*Mm];

__device__ __forceinline__ ull pack2(float a, float b){
    ull r; asm("mov.b64 %0, {%1,%2};" : "=l"(r) : "f"(a), "f"(b)); return r;
}
__device__ __forceinline__ ull fma2(ull a, ull b, ull c){
    ull d; asm("fma.rn.f32x2 %0, %1, %2, %3;" : "=l"(d) : "l"(a), "l"(b), "l"(c)); return d;
}
__device__ __forceinline__ ull add2(ull a, ull b){
    ull d; asm("add.rn.f32x2 %0, %1, %2;" : "=l"(d) : "l"(a), "l"(b)); return d;
}
__device__ __forceinline__ float2 unp(ull a){
    float2 f; asm("mov.b64 {%0,%1}, %2;" : "=f"(f.x), "=f"(f.y) : "l"(a)); return f;
}
__device__ __forceinline__ float lo2(ull a){ return unp(a).x; }

__global__ void enc_kernel(const float* __restrict__ xa,
                           const float* __restrict__ ew,
                           const float* __restrict__ eb)
{
    __shared__ float sx[INF_];
    int nrow = blockIdx.x;
    if (threadIdx.x < INF_) sx[threadIdx.x] = xa[nrow*INF_ + threadIdx.x];
    __syncthreads();
    int h = threadIdx.x;
    float a = eb[h];
    #pragma unroll
    for (int i = 0; i < INF_; i++) a = fmaf(sx[i], ew[i*Hh + h], a);
    g_feats[nrow*Hh + h] = a;
}

// ---- shared layout (float units) ----
#define OFF_NSW  0                   // 32768: ns_w as ull[256][64]
#define OFF_PART 32768               // 8192:  partials (4096 ull)
#define OFF_X2   (OFF_PART+8192)     // 4096:  x splat ull[8][256]
#define OFF_QN   (OFF_X2+4096)       // 5008:  u16[10016]
#define OFF_TACT (OFF_QN+5008)       // 1000
#define OFF_AW   (OFF_TACT+Nn)       // 256
#define OFF_NSB  (OFF_AW+256)        // 128
#define OFF_NMB  (OFF_NSB+128)       // 128
#define OFF_G    (OFF_NMB+128)       // 128
#define OFF_NBR  (OFF_G+128)         // 128 ints
#define OFF_LN   (OFF_NBR+128)       // 8 ints
#define OFF_LI   (OFF_LN+8)          // 8 ints
#define OFF_NA   (OFF_LI+8)          // 8
#define OFF_ACTP (OFF_NA+8)          // 32
#define OFF_CTL  (OFF_ACTP+32)       // 8 ints: head,tail,pc,done,m
#define OFF_AB   (OFF_CTL+8)
#define SMEM_FLOATS (OFF_AB+4)
#define SMEM_BYTES  (SMEM_FLOATS*4)

// warp 0: commit prev window's tail/pc, then select next window (<=Bw
// productive entries with pairwise-distinct nodes, stop at first repeat)
__device__ __forceinline__ void scan_window(float* sm, int lane, int mprev)
{
    int* ctl = (int*)(sm + OFF_CTL);
    u16* qn  = (u16*)(sm + OFF_QN);
    float* tact = sm + OFF_TACT;
    int* ln = (int*)(sm + OFF_LN);
    int* li = (int*)(sm + OFF_LI);
    if (lane == 0) { ctl[2] += mprev; ctl[1] += DEGc*mprev; }
    __syncwarp();
    int head = ctl[0], tail = ctl[1];
    int lim = tail < MAXM ? tail : MAXM;
    int mq = 0;
    while (head < lim && mq < Bw) {
        int bl = lim - head; if (bl > 32) bl = 32;
        bool valid = lane < bl;
        int nodel = valid ? (int)qn[head + lane] : -1;
        float ta = valid ? tact[nodel] : 2.0f;
        unsigned prod  = __ballot_sync(0xffffffffu, valid && ta <= THRv);
        unsigned peers = __match_any_sync(0xffffffffu, nodel);
        bool dup = false;
        if ((prod >> lane) & 1) {
            dup = (peers & prod & ((1u << lane) - 1u)) != 0;
            for (int i = 0; i < mq; i++) dup |= (nodel == ln[i]);
        }
        unsigned badm = __ballot_sync(0xffffffffu, dup);
        unsigned keep = prod; int adv = bl; bool stop = false;
        if (badm) { adv = __ffs(badm) - 1; keep &= (1u << adv) - 1u; stop = true; }
        int room = Bw - mq, cnt = __popc(keep);
        if (cnt > room) {
            unsigned k2 = keep;
            for (int z = 0; z < room; z++) k2 &= (k2 - 1u);
            int clip = __ffs(k2) - 1;
            keep &= (1u << clip) - 1u; adv = clip; cnt = room; stop = true;
        }
        if ((keep >> lane) & 1) {
            int rk = __popc(keep & ((1u << lane) - 1u));
            ln[mq + rk] = nodel; li[mq + rk] = head + lane;
        }
        __syncwarp();
        mq += cnt; head += adv;
        if (stop) break;
    }
    if (lane == 0) { ctl[0] = head; ctl[4] = mq; if (mq == 0) ctl[3] = 1; }
}

__global__ void __launch_bounds__(1024, 1) serial_kernel(
    const float* __restrict__ fm,  const int*   __restrict__ nbr,
    const float* __restrict__ nsw, const float* __restrict__ nsb,
    const float* __restrict__ nmw, const float* __restrict__ nmb,
    const float* __restrict__ aw,  const float* __restrict__ ab,
    const float* __restrict__ dw,  const float* __restrict__ db,
    float* __restrict__ out)
{
    extern __shared__ float sm[];
    ull*   s_nsw2 = (ull*)(sm + OFF_NSW);
    ull*   s_part2= (ull*)(sm + OFF_PART);
    ull*   s_x2u  = (ull*)(sm + OFF_X2);
    u16*   s_qn16 = (u16*)(sm + OFF_QN);
    float* s_tact = sm + OFF_TACT;
    float* s_aw   = sm + OFF_AW;
    float* s_nsb  = sm + OFF_NSB;
    float* s_nmb  = sm + OFF_NMB;
    float* s_g    = sm + OFF_G;
    int*   s_nbr  = (int*)(sm + OFF_NBR);
    int*   s_ln   = (int*)(sm + OFF_LN);
    int*   s_li   = (int*)(sm + OFF_LI);
    float* s_na   = sm + OFF_NA;
    float* s_actp = sm + OFF_ACTP;
    int*   ctl    = (int*)(sm + OFF_CTL);

    const int t = threadIdx.x;
    const int w = t >> 5, l = t & 31;

    for (int i = t; i < (256*Hh)/4; i += 1024)
        ((float4*)(sm + OFF_NSW))[i] = ((const float4*)nsw)[i];
    if (t < 256) s_aw[t] = aw[t];
    if (t < 128) { s_nsb[t] = nsb[t]; s_nmb[t] = nmb[t]; s_g[t] = 0.f; }
    if (t < Nn)  s_tact[t] = 0.f;
    if (t < NSTART) s_qn16[t] = (u16)t;
    if (t == 0) {
        ctl[0] = 0; ctl[1] = NSTART; ctl[2] = 0; ctl[3] = 0;
        sm[OFF_AB] = ab[0];
    }
    // nm_w in regs: rows [16*(w>>1), +16), pair-col ((w&1)<<5)|l
    ull wnm[16];
    {
        int kc = w >> 1, j2 = ((w & 1) << 5) | l;
        #pragma unroll
        for (int i = 0; i < 16; i++) {
            float2 v = *(const float2*)(nmw + (16*kc + i)*Hh + 2*j2);
            wnm[i] = pack2(v.x, v.y);
        }
    }
    __syncthreads();

    int mprev = 0;
    for (;;) {
        if (w == 0) scan_window(sm, l, mprev);
        __syncthreads();
        if (ctl[3]) break;
        const int m = ctl[4], tail = ctl[1], pcb = ctl[2];
        mprev = m;

        // ---- G: gather x (splatted), act partials, neighbors ----
        {
            int e = t >> 7, k = t & 127;
            if (e < m) {
                int node = s_ln[e], idx = s_li[e];
                float f1 = g_feats[node*Hh + k];
                const float* mp = (idx < NSTART) ? (fm + idx*Mm)
                                 : (g_msgs + ((idx - NSTART) >> 4)*Mm);
                float f2 = mp[k];
                s_x2u[e*256 + k]       = pack2(f1, f1);
                s_x2u[e*256 + 128 + k] = pack2(f2, f2);
                float ap = f1*s_aw[k] + f2*s_aw[128 + k];
                #pragma unroll
                for (int o = 16; o; o >>= 1) ap += __shfl_xor_sync(0xffffffffu, ap, o);
                if (l == 0) s_actp[e*4 + ((t >> 5) & 3)] = ap;
                if (k < DEGc) s_nbr[e*DEGc + k] = nbr[node*DEGc + k];
            }
        }
        __syncthreads();

        // ---- NS: batched partials, each weight serves 4 entries ----
        {
            int eh = w >> 4, w4 = w & 15, kc = w4 >> 1, j2 = ((w4 & 1) << 5) | l;
            const ull* wb = s_nsw2 + (size_t)(kc*32)*64 + j2;
            const ull* xb = s_x2u + (eh*4)*256 + kc*32;
            ull a0=0, a1=0, a2=0, a3=0;
            #pragma unroll
            for (int kk = 0; kk < 32; kk++) {
                ull wv = wb[kk*64];
                a0 = fma2(xb[kk],       wv, a0);
                a1 = fma2(xb[256 + kk], wv, a1);
                a2 = fma2(xb[512 + kk], wv, a2);
                a3 = fma2(xb[768 + kk], wv, a3);
            }
            ull* pp = s_part2 + (size_t)(eh*4)*512 + kc*64 + j2;
            pp[0] = a0; pp[512] = a1; pp[1024] = a2; pp[1536] = a3;
        }
        __syncthreads();

        // ---- R: ns reduce/relu/splat ; act+tact ; enqueue ----
        if (t < 512) {
            int e = t >> 6, j2 = t & 63;
            ull s = s_part2[e*512 + j2];
            #pragma unroll
            for (int kc = 1; kc < 8; kc++) s = add2(s, s_part2[e*512 + kc*64 + j2]);
            float2 v = unp(s);
            float v0 = fmaxf(v.x + s_nsb[2*j2],     0.f);
            float v1 = fmaxf(v.y + s_nsb[2*j2 + 1], 0.f);
            s_x2u[e*256 + 2*j2]     = pack2(v0, v0);
            s_x2u[e*256 + 2*j2 + 1] = pack2(v1, v1);
        } else if (t < 520) {
            int e = t - 512;
            if (e < m) {
                float z = sm[OFF_AB] + s_actp[e*4] + s_actp[e*4+1]
                        + s_actp[e*4+2] + s_actp[e*4+3];
                float cand = 1.f / (1.f + expf(-z));
                int node = s_ln[e];
                float ta = s_tact[node];
                float na = (ta + cand > 1.0f) ? (1.0f - ta) : cand;
                s_na[e] = na;
                s_tact[node] = ta + na;
            }
        } else if (t >= 640 && t < 768) {
            int rel = t - 640, e = rel >> 4, d = rel & 15;
            if (e < m) {
                int qp = tail + e*DEGc + d;
                if (qp < QCAP) s_qn16[qp] = (u16)s_nbr[e*DEGc + d];
            }
        }
        __syncthreads();

        // ---- NM + commit, two passes of 4 entries ----
        for (int pq = 0; pq < 2; pq++) {
            {
                int kc = w >> 1, j2 = ((w & 1) << 5) | l;
                const ull* xb = s_x2u + (pq*4)*256 + kc*16;
                ull a0=0, a1=0, a2=0, a3=0;
                #pragma unroll
                for (int kk = 0; kk < 16; kk++) {
                    ull wv = wnm[kk];
                    a0 = fma2(xb[kk],       wv, a0);
                    a1 = fma2(xb[256 + kk], wv, a1);
                    a2 = fma2(xb[512 + kk], wv, a2);
                    a3 = fma2(xb[768 + kk], wv, a3);
                }
                ull* pp = s_part2 + kc*64 + j2;
                pp[0] = a0; pp[1024] = a1; pp[2048] = a2; pp[3072] = a3;
            }
            __syncthreads();
            if (t < 256) {
                int el = t >> 6, j2 = t & 63, e = pq*4 + el;
                if (e < m) {
                    int pcg = pcb + e;
                    if (pcg < MSGCAP) {
                        ull s = s_part2[el*1024 + j2];
                        #pragma unroll
                        for (int kc = 1; kc < 16; kc++)
                            s = add2(s, s_part2[el*1024 + kc*64 + j2]);
                        float2 v = unp(s);
                        float2 o; o.x = v.x + s_nmb[2*j2]; o.y = v.y + s_nmb[2*j2+1];
                        *(float2*)(g_msgs + pcg*Mm + 2*j2) = o;
                    }
                }
            } else if (t < 768) {
                int rel = t - 256, el = rel >> 7, k = rel & 127, e = pq*4 + el;
                if (e < m) g_feats[s_ln[e]*Hh + k] = lo2(s_x2u[e*256 + k]);
            } else if (t < 896) {
                int k = t - 768;
                float acc = s_g[k];
                #pragma unroll
                for (int el = 0; el < 4; el++) {
                    int e = pq*4 + el;
                    if (e < m) acc = fmaf(lo2(s_x2u[e*256 + k]), s_na[e], acc);
                }
                s_g[k] = acc;
            }
            __syncthreads();
        }
    }

    // ---- decode + log_softmax ----
    float* scratch = sm + OFF_PART;
    if (t < Pp*OUTn) {
        int p = t / OUTn, o = t % OUTn;
        float z = db[p*OUTn + o];
        #pragma unroll 8
        for (int h = 0; h < Hh; h++) z = fmaf(s_g[h], dw[(p*Hh + h)*OUTn + o], z);
        scratch[t] = z;
    }
    __syncthreads();
    if (t < Pp) {
        float mx = -1e30f;
        for (int o = 0; o < OUTn; o++) mx = fmaxf(mx, scratch[t*OUTn + o]);
        float se = 0.f;
        for (int o = 0; o < OUTn; o++) se += expf(scratch[t*OUTn + o] - mx);
        float ls = logf(se);
        for (int o = 0; o < OUTn; o++) out[t*OUTn + o] = scratch[t*OUTn + o] - mx - ls;
    }
}

extern "C" void kernel_launch(void* const* d_in, const int* in_sizes, int n_in,
                              void* d_out, int out_size)
{
    const float* xa  = (const float*)d_in[0];
    const float* fm  = (const float*)d_in[1];
    const int*   nbv = (const int*)  d_in[2];
    const float* ew  = (const float*)d_in[4];
    const float* eb  = (const float*)d_in[5];
    const float* nsw = (const float*)d_in[6];
    const float* nsb = (const float*)d_in[7];
    const float* nmw = (const float*)d_in[8];
    const float* nmb = (const float*)d_in[9];
    const float* aw  = (const float*)d_in[10];
    const float* ab  = (const float*)d_in[11];
    const float* dw  = (const float*)d_in[12];
    const float* db  = (const float*)d_in[13];
    float* out = (float*)d_out;

    cudaFuncSetAttribute(serial_kernel,
                         cudaFuncAttributeMaxDynamicSharedMemorySize, SMEM_BYTES);

    enc_kernel<<<Nn, Hh>>>(xa, ew, eb);
    serial_kernel<<<1, 1024, SMEM_BYTES>>>(fm, nbv, nsw, nsb, nmw, nmb,
                                           aw, ab, dw, db, out);
}

// round 7
// speedup vs baseline: 1.6555x; 1.6555x over previous
#include <cuda_runtime.h>

#define Nn      1000
#define INF_    32
#define Hh      128
#define Mm      128
#define DEGc    16
#define Pp      2
#define OUTn    10
#define NSTART  64
#define MAXM    10000
#define QCAP    10016
#define MSGCAP  640
#define Bw      8
#define THRv    (1.0f - 1e-7f)

typedef unsigned long long ull;
typedef unsigned short u16;

__device__ float g_feats[Nn*Hh];
__device__ float g_msgs[MSGCAP*Mm];

__device__ __forceinline__ ull pack2(float a, float b){
    ull r; asm("mov.b64 %0, {%1,%2};" : "=l"(r) : "f"(a), "f"(b)); return r;
}
__device__ __forceinline__ ull fma2(ull a, ull b, ull c){
    ull d; asm("fma.rn.f32x2 %0, %1, %2, %3;" : "=l"(d) : "l"(a), "l"(b), "l"(c)); return d;
}
__device__ __forceinline__ ull add2(ull a, ull b){
    ull d; asm("add.rn.f32x2 %0, %1, %2;" : "=l"(d) : "l"(a), "l"(b)); return d;
}
__device__ __forceinline__ float2 unp(ull a){
    float2 f; asm("mov.b64 {%0,%1}, %2;" : "=f"(f.x), "=f"(f.y) : "l"(a)); return f;
}
__device__ __forceinline__ float lo2(ull a){ return unp(a).x; }

__global__ void enc_kernel(const float* __restrict__ xa,
                           const float* __restrict__ ew,
                           const float* __restrict__ eb)
{
    __shared__ float sx[INF_];
    int nrow = blockIdx.x;
    if (threadIdx.x < INF_) sx[threadIdx.x] = xa[nrow*INF_ + threadIdx.x];
    __syncthreads();
    int h = threadIdx.x;
    float a = eb[h];
    #pragma unroll
    for (int i = 0; i < INF_; i++) a = fmaf(sx[i], ew[i*Hh + h], a);
    g_feats[nrow*Hh + h] = a;
}

// ---- shared layout (float units) ----
#define OFF_NSW  0
#define OFF_PART 32768
#define OFF_X2   (OFF_PART+8192)
#define OFF_QN   (OFF_X2+4096)
#define OFF_TACT (OFF_QN+5008)
#define OFF_AW   (OFF_TACT+Nn)
#define OFF_NSB  (OFF_AW+256)
#define OFF_NMB  (OFF_NSB+128)
#define OFF_G    (OFF_NMB+128)
#define OFF_NBR  (OFF_G+128)
#define OFF_LN   (OFF_NBR+128)
#define OFF_LI   (OFF_LN+8)
#define OFF_NA   (OFF_LI+8)
#define OFF_ACTP (OFF_NA+8)
#define OFF_CTL  (OFF_ACTP+32)
#define OFF_AB   (OFF_CTL+8)
#define SMEM_FLOATS (OFF_AB+4)
#define SMEM_BYTES  (SMEM_FLOATS*4)

// warp 0: select <=Bw productive node-distinct entries; duplicates are
// DEFERRED (head rewinds to first deferred; selections past it are flagged
// consumed via bit15 so future scans skip them).
__device__ __forceinline__ void scan_window(float* sm, int lane, int mprev)
{
    int* ctl = (int*)(sm + OFF_CTL);
    u16* qn  = (u16*)(sm + OFF_QN);
    float* tact = sm + OFF_TACT;
    int* ln = (int*)(sm + OFF_LN);
    int* li = (int*)(sm + OFF_LI);
    if (lane == 0) { ctl[2] += mprev; ctl[1] += DEGc*mprev; }
    __syncwarp();
    int pos = ctl[0], tail = ctl[1];
    int lim = tail < MAXM ? tail : MAXM;
    int mq = 0, rewind = -1;
    while (pos < lim && mq < Bw) {
        int bl = lim - pos; if (bl > 32) bl = 32;
        int idx = pos + lane;
        bool valid = lane < bl;
        int raw = valid ? (int)qn[idx] : 0x8000;
        int nodel = raw & 0x7FFF;
        bool cons = (raw & 0x8000) != 0;
        float ta = (valid && !cons) ? tact[nodel] : 2.0f;
        unsigned prod = __ballot_sync(~0u, valid && !cons && ta <= THRv);
        unsigned peers = __match_any_sync(~0u, nodel);
        bool dup = false;
        if ((prod >> lane) & 1) {
            dup = (peers & prod & ((1u << lane) - 1u)) != 0;
            for (int i = 0; i < mq; i++) dup |= (nodel == ln[i]);
        }
        unsigned dupm = __ballot_sync(~0u, dup);
        unsigned keep = prod & ~dupm;
        int room = Bw - mq, cnt = __popc(keep);
        int clip = 33;
        if (cnt > room) {
            unsigned k2 = keep;
            for (int z = 0; z < room; z++) k2 &= k2 - 1u;
            clip = __ffs(k2) - 1;
            keep &= (1u << clip) - 1u;
            cnt = room;
        }
        unsigned defer = dupm & ((clip < 33) ? ((1u << clip) - 1u) : ~0u);
        int firstdef = defer ? (pos + __ffs(defer) - 1)
                             : (clip < 33 ? pos + clip : -1);
        if ((keep >> lane) & 1) {
            int rk = __popc(keep & ((1u << lane) - 1u));
            ln[mq + rk] = nodel; li[mq + rk] = idx;
            qn[idx] = (u16)(raw | 0x8000);
        }
        __syncwarp();
        mq += cnt;
        if (firstdef >= 0 && rewind < 0) rewind = firstdef;
        pos += bl;
        if (clip < 33) break;
    }
    if (lane == 0) {
        ctl[0] = (rewind >= 0) ? rewind : pos;
        ctl[4] = mq;
        if (mq == 0) ctl[3] = 1;
    }
}

__global__ void __launch_bounds__(1024, 1) serial_kernel(
    const float* __restrict__ fm,  const int*   __restrict__ nbr,
    const float* __restrict__ nsw, const float* __restrict__ nsb,
    const float* __restrict__ nmw, const float* __restrict__ nmb,
    const float* __restrict__ aw,  const float* __restrict__ ab,
    const float* __restrict__ dw,  const float* __restrict__ db,
    float* __restrict__ out)
{
    extern __shared__ float sm[];
    ull*   s_nsw2 = (ull*)(sm + OFF_NSW);
    ull*   s_part2= (ull*)(sm + OFF_PART);
    ull*   s_x2u  = (ull*)(sm + OFF_X2);
    u16*   s_qn16 = (u16*)(sm + OFF_QN);
    float* s_tact = sm + OFF_TACT;
    float* s_aw   = sm + OFF_AW;
    float* s_nsb  = sm + OFF_NSB;
    float* s_nmb  = sm + OFF_NMB;
    float* s_g    = sm + OFF_G;
    int*   s_nbr  = (int*)(sm + OFF_NBR);
    int*   s_ln   = (int*)(sm + OFF_LN);
    float* s_na   = sm + OFF_NA;
    float* s_actp = sm + OFF_ACTP;
    int*   ctl    = (int*)(sm + OFF_CTL);

    const int t = threadIdx.x;
    const int w = t >> 5, l = t & 31;

    for (int i = t; i < (256*Hh)/4; i += 1024)
        ((float4*)(sm + OFF_NSW))[i] = ((const float4*)nsw)[i];
    if (t < 256) s_aw[t] = aw[t];
    if (t < 128) { s_nsb[t] = nsb[t]; s_nmb[t] = nmb[t]; s_g[t] = 0.f; }
    if (t < Nn)  s_tact[t] = 0.f;
    if (t < NSTART) s_qn16[t] = (u16)t;
    if (t == 0) {
        ctl[0] = 0; ctl[1] = NSTART; ctl[2] = 0; ctl[3] = 0;
        sm[OFF_AB] = ab[0];
    }
    ull wnm[16];
    {
        int kc = w >> 1, j2 = ((w & 1) << 5) | l;
        #pragma unroll
        for (int i = 0; i < 16; i++) {
            float2 v = *(const float2*)(nmw + (16*kc + i)*Hh + 2*j2);
            wnm[i] = pack2(v.x, v.y);
        }
    }
    __syncthreads();

    int mprev = 0;
    for (;;) {
        if (w == 0) scan_window(sm, l, mprev);
        __syncthreads();
        if (ctl[3]) break;
        const int m = ctl[4], tail = ctl[1], pcb = ctl[2];
        mprev = m;

        // ---- G: gather x (splatted), act partials, neighbors ----
        {
            int e = t >> 7, k = t & 127;
            if (e < m) {
                int node = s_ln[e], idx = ((int*)(sm + OFF_LI))[e];
                float f1 = g_feats[node*Hh + k];
                const float* mp = (idx < NSTART) ? (fm + idx*Mm)
                                 : (g_msgs + ((idx - NSTART) >> 4)*Mm);
                float f2 = mp[k];
                s_x2u[e*256 + k]       = pack2(f1, f1);
                s_x2u[e*256 + 128 + k] = pack2(f2, f2);
                float ap = f1*s_aw[k] + f2*s_aw[128 + k];
                #pragma unroll
                for (int o = 16; o; o >>= 1) ap += __shfl_xor_sync(0xffffffffu, ap, o);
                if (l == 0) s_actp[e*4 + ((t >> 5) & 3)] = ap;
                if (k < DEGc) s_nbr[e*DEGc + k] = nbr[node*DEGc + k];
            }
        }
        __syncthreads();

        // ---- NS: batched partials ----
        {
            int eh = w >> 4, w4 = w & 15, kc = w4 >> 1, j2 = ((w4 & 1) << 5) | l;
            const ull* wb = s_nsw2 + (size_t)(kc*32)*64 + j2;
            const ull* xb = s_x2u + (eh*4)*256 + kc*32;
            ull a0=0, a1=0, a2=0, a3=0;
            #pragma unroll
            for (int kk = 0; kk < 32; kk++) {
                ull wv = wb[kk*64];
                a0 = fma2(xb[kk],       wv, a0);
                a1 = fma2(xb[256 + kk], wv, a1);
                a2 = fma2(xb[512 + kk], wv, a2);
                a3 = fma2(xb[768 + kk], wv, a3);
            }
            ull* pp = s_part2 + (size_t)(eh*4)*512 + kc*64 + j2;
            pp[0] = a0; pp[512] = a1; pp[1024] = a2; pp[1536] = a3;
        }
        __syncthreads();

        // ---- R: ns reduce/relu/splat ; act+tact ; enqueue ----
        if (t < 512) {
            int e = t >> 6, j2 = t & 63;
            ull s = s_part2[e*512 + j2];
            #pragma unroll
            for (int kc = 1; kc < 8; kc++) s = add2(s, s_part2[e*512 + kc*64 + j2]);
            float2 v = unp(s);
            float v0 = fmaxf(v.x + s_nsb[2*j2],     0.f);
            float v1 = fmaxf(v.y + s_nsb[2*j2 + 1], 0.f);
            s_x2u[e*256 + 2*j2]     = pack2(v0, v0);
            s_x2u[e*256 + 2*j2 + 1] = pack2(v1, v1);
        } else if (t < 520) {
            int e = t - 512;
            if (e < m) {
                float z = sm[OFF_AB] + s_actp[e*4] + s_actp[e*4+1]
                        + s_actp[e*4+2] + s_actp[e*4+3];
                float cand = 1.f / (1.f + expf(-z));
                int node = s_ln[e];
                float ta = s_tact[node];
                float na = (ta + cand > 1.0f) ? (1.0f - ta) : cand;
                s_na[e] = na;
                s_tact[node] = ta + na;
            }
        } else if (t >= 640 && t < 768) {
            int rel = t - 640, e = rel >> 4, d = rel & 15;
            if (e < m) {
                int qp = tail + e*DEGc + d;
                if (qp < QCAP) s_qn16[qp] = (u16)s_nbr[e*DEGc + d];
            }
        }
        __syncthreads();

        // ---- NM + commit, two passes of 4 entries ----
        for (int pq = 0; pq < 2; pq++) {
            {
                int kc = w >> 1, j2 = ((w & 1) << 5) | l;
                const ull* xb = s_x2u + (pq*4)*256 + kc*16;
                ull a0=0, a1=0, a2=0, a3=0;
                #pragma unroll
                for (int kk = 0; kk < 16; kk++) {
                    ull wv = wnm[kk];
                    a0 = fma2(xb[kk],       wv, a0);
                    a1 = fma2(xb[256 + kk], wv, a1);
                    a2 = fma2(xb[512 + kk], wv, a2);
                    a3 = fma2(xb[768 + kk], wv, a3);
                }
                ull* pp = s_part2 + kc*64 + j2;
                pp[0] = a0; pp[1024] = a1; pp[2048] = a2; pp[3072] = a3;
            }
            __syncthreads();
            if (t < 256) {
                int el = t >> 6, j2 = t & 63, e = pq*4 + el;
                if (e < m) {
                    int pcg = pcb + e;
                    if (pcg < MSGCAP) {
                        ull s = s_part2[el*1024 + j2];
                        #pragma unroll
                        for (int kc = 1; kc < 16; kc++)
                            s = add2(s, s_part2[el*1024 + kc*64 + j2]);
                        float2 v = unp(s);
                        float2 o; o.x = v.x + s_nmb[2*j2]; o.y = v.y + s_nmb[2*j2+1];
                        *(float2*)(g_msgs + pcg*Mm + 2*j2) = o;
                    }
                }
            } else if (t < 768) {
                int rel = t - 256, el = rel >> 7, k = rel & 127, e = pq*4 + el;
                if (e < m) g_feats[s_ln[e]*Hh + k] = lo2(s_x2u[e*256 + k]);
            } else if (t < 896) {
                int k = t - 768;
                float acc = s_g[k];
                #pragma unroll
                for (int el = 0; el < 4; el++) {
                    int e = pq*4 + el;
                    if (e < m) acc = fmaf(lo2(s_x2u[e*256 + k]), s_na[e], acc);
                }
                s_g[k] = acc;
            }
            __syncthreads();
        }
    }

    // ---- decode + log_softmax ----
    float* scratch = sm + OFF_PART;
    if (t < Pp*OUTn) {
        int p = t / OUTn, o = t % OUTn;
        float z = db[p*OUTn + o];
        #pragma unroll 8
        for (int h = 0; h < Hh; h++) z = fmaf(s_g[h], dw[(p*Hh + h)*OUTn + o], z);
        scratch[t] = z;
    }
    __syncthreads();
    if (t < Pp) {
        float mx = -1e30f;
        for (int o = 0; o < OUTn; o++) mx = fmaxf(mx, scratch[t*OUTn + o]);
        float se = 0.f;
        for (int o = 0; o < OUTn; o++) se += expf(scratch[t*OUTn + o] - mx);
        float ls = logf(se);
        for (int o = 0; o < OUTn; o++) out[t*OUTn + o] = scratch[t*OUTn + o] - mx - ls;
    }
}

extern "C" void kernel_launch(void* const* d_in, const int* in_sizes, int n_in,
                              void* d_out, int out_size)
{
    const float* xa  = (const float*)d_in[0];
    const float* fm  = (const float*)d_in[1];
    const int*   nbv = (const int*)  d_in[2];
    const float* ew  = (const float*)d_in[4];
    const float* eb  = (const float*)d_in[5];
    const float* nsw = (const float*)d_in[6];
    const float* nsb = (const float*)d_in[7];
    const float* nmw = (const float*)d_in[8];
    const float* nmb = (const float*)d_in[9];
    const float* aw  = (const float*)d_in[10];
    const float* ab  = (const float*)d_in[11];
    const float* dw  = (const float*)d_in[12];
    const float* db  = (const float*)d_in[13];
    float* out = (float*)d_out;

    cudaFuncSetAttribute(serial_kernel,
                         cudaFuncAttributeMaxDynamicSharedMemorySize, SMEM_BYTES);

    enc_kernel<<<Nn, Hh>>>(xa, ew, eb);
    serial_kernel<<<1, 1024, SMEM_BYTES>>>(fm, nbv, nsw, nsb, nmw, nmb,
                                           aw, ab, dw, db, out);
}